// round 12
// baseline (speedup 1.0000x reference)
#include <cuda_runtime.h>
#include <cstdint>

#define BB    64
#define TOPK  2
#define EE    16
#define CC    1024
#define KK    4096
#define NTOK  (BB * TOPK)     // 128

#define WARPS  8
#define RPW    4               // rows per warp (consume)
#define TCH    8               // tokens per chunk
#define CTILE  (WARPS * RPW)   // 32 rows per CTA
#define K4     (KK / 4)        // 1024 float4 per row
#define JITERS (K4 / 32)       // 32 k-steps (512B per row per step)
#define NSTAGE 4

// stage = w [CTILE][32] f4 (16KB) + a [TCH][32] f4 (4KB) = 20KB contiguous
#define W_ST_F4   (CTILE * 32)                 // 1024
#define A_ST_F4   (TCH * 32)                   // 256
#define ST_F4     (W_ST_F4 + A_ST_F4)          // 1280
#define ST_BYTES  (ST_F4 * 16)                 // 20480
#define DYN_BYTES (NSTAGE * ST_BYTES)          // 81920

__device__ float g_tmp[NTOK * CC];

// ---- PTX helpers -----------------------------------------------------------
// Bulk async copy global->shared, completion via mbarrier complete_tx.
__device__ __forceinline__ void bulk_cp(uint32_t dst, const void* src,
                                        uint32_t bytes, uint32_t mbar) {
    asm volatile(
        "cp.async.bulk.shared::cta.global.mbarrier::complete_tx::bytes "
        "[%0], [%1], %2, [%3];"
        :: "r"(dst), "l"(src), "r"(bytes), "r"(mbar) : "memory");
}
__device__ __forceinline__ void mbar_init(uint32_t mbar, uint32_t count) {
    asm volatile("mbarrier.init.shared.b64 [%0], %1;"
                 :: "r"(mbar), "r"(count) : "memory");
}
__device__ __forceinline__ void mbar_expect_tx(uint32_t mbar, uint32_t tx) {
    asm volatile("mbarrier.arrive.expect_tx.shared.b64 _, [%0], %1;"
                 :: "r"(mbar), "r"(tx) : "memory");
}
__device__ __forceinline__ void mbar_wait(uint32_t mbar, uint32_t parity) {
    asm volatile(
        "{\n\t"
        ".reg .pred P;\n\t"
        "WL_%=:\n\t"
        "mbarrier.try_wait.parity.acquire.cta.shared::cta.b64 P, [%0], %1, 0x989680;\n\t"
        "@P bra.uni WD_%=;\n\t"
        "bra.uni WL_%=;\n\t"
        "WD_%=:\n\t"
        "}"
        :: "r"(mbar), "r"(parity) : "memory");
}
__device__ __forceinline__ void ffma2(unsigned long long& acc,
                                      unsigned long long w,
                                      unsigned long long a) {
    asm("fma.rn.f32x2 %0, %1, %2, %0;" : "+l"(acc) : "l"(w), "l"(a));
}
__device__ __forceinline__ float pair_sum(unsigned long long p) {
    float lo, hi;
    asm("mov.b64 {%0, %1}, %2;" : "=f"(lo), "=f"(hi) : "l"(p));
    return lo + hi;
}

// ---------------------------------------------------------------------------
// Grouped expert matvec — async-DMA producer (UBLKCP + mbarrier).
// Grid (2, CC/CTILE=32, EE=16): x = token-chunk (fastest -> pair CTAs sharing
// a weight tile are bid-adjacent -> L2 dedup), y = c-tile, z = expert.
// Block 256 (8 warps), occ 2. 4-stage ring, refill distance 3 (60KB in
// flight per CTA, driven by the DMA engine). Per stage: each warp's lane 0
// issues 5 x 512B bulk copies; warp 0 posts expect_tx(20480). Consumers do
// HW-sleep mbarrier waits; no per-thread LDGSTS, streams bypass L1.
// ---------------------------------------------------------------------------
__global__ void __launch_bounds__(256, 2)
matvec(const float* __restrict__ act,
       const float* __restrict__ W,
       const int*  __restrict__ eidx) {
    extern __shared__ float4 st[];              // [NSTAGE][1280] f4
    __shared__ __align__(8) unsigned long long mbar_s[NSTAGE];
    __shared__ int se[NTOK];
    __shared__ int stok[NTOK];

    const int tid = threadIdx.x;
    const int e   = blockIdx.z;

    if (tid == 0) {
#pragma unroll
        for (int s = 0; s < NSTAGE; ++s)
            mbar_init((uint32_t)__cvta_generic_to_shared(&mbar_s[s]), 1);
        asm volatile("fence.proxy.async.shared::cta;" ::: "memory");
    }
    if (tid < NTOK) se[tid] = eidx[tid];
    __syncthreads();                            // orders mbar init too
    int mine = (tid < NTOK) && (se[tid] == e);
    if (mine) {
        int pos = 0;
        for (int j = 0; j < tid; ++j) pos += (se[j] == e) ? 1 : 0;
        stok[pos] = tid;
    }
    const int cnt = __syncthreads_count(mine);
    if (cnt == 0) return;

    const int warp = tid >> 5;
    const int lane = tid & 31;
    const int c0   = blockIdx.y * CTILE;
    const int off  = (blockIdx.y + blockIdx.z * 5) & (JITERS - 1);  // k stagger

    // source rows this warp stages: c0 + warp + 8i  (i = 0..3)
    const float* wrow[4];
#pragma unroll
    for (int i = 0; i < 4; ++i)
        wrow[i] = W + (size_t)(e * CC + c0 + warp + 8 * i) * KK;

    const uint32_t st0 = (uint32_t)__cvta_generic_to_shared(st);
    uint32_t mb[NSTAGE];
#pragma unroll
    for (int s = 0; s < NSTAGE; ++s)
        mb[s] = (uint32_t)__cvta_generic_to_shared(&mbar_s[s]);

    for (int t0 = blockIdx.x * TCH; t0 < cnt; t0 += 2 * TCH) {
        int myt = t0 + warp;
        if (myt >= cnt) myt = cnt - 1;          // tail clamp (dup staging harmless)
        const float* asrc = act + (size_t)stok[myt] * KK;

        unsigned long long acc[RPW][TCH];
#pragma unroll
        for (int r = 0; r < RPW; ++r)
#pragma unroll
            for (int t = 0; t < TCH; ++t) acc[r][t] = 0ull;

        // ---- prime stages 0 .. NSTAGE-2 ----
#pragma unroll
        for (int s = 0; s < NSTAGE - 1; ++s) {
            const int ks = (s + off) & (JITERS - 1);
            if (lane == 0) {
                if (warp == 0) mbar_expect_tx(mb[s], ST_BYTES);
                const uint32_t d = st0 + s * ST_BYTES;
#pragma unroll
                for (int i = 0; i < 4; ++i)
                    bulk_cp(d + (warp + 8 * i) * 512, wrow[i] + ks * 128, 512, mb[s]);
                bulk_cp(d + 16384 + warp * 512, asrc + ks * 128, 512, mb[s]);
            }
        }

#pragma unroll 1
        for (int j = 0; j < JITERS; ++j) {
            mbar_wait(mb[j & (NSTAGE - 1)], (j >> 2) & 1);
            __syncthreads();                    // all warps done with slot (j-1)&3

            const int jf = j + NSTAGE - 1;
            if (jf < JITERS && lane == 0) {
                const int kf = (jf + off) & (JITERS - 1);
                const int sf = jf & (NSTAGE - 1);
                if (warp == 0) mbar_expect_tx(mb[sf], ST_BYTES);
                const uint32_t d = st0 + sf * ST_BYTES;
#pragma unroll
                for (int i = 0; i < 4; ++i)
                    bulk_cp(d + (warp + 8 * i) * 512, wrow[i] + kf * 128, 512, mb[sf]);
                bulk_cp(d + 16384 + warp * 512, asrc + kf * 128, 512, mb[sf]);
            }

            // ---- consume stage j & 3 ----
            const ulonglong2* base = reinterpret_cast<const ulonglong2*>(
                st + (size_t)(j & (NSTAGE - 1)) * ST_F4);
            const ulonglong2* wb = base + (warp * RPW) * 32 + lane;
            const ulonglong2* ab = base + W_ST_F4 + lane;

            ulonglong2 wv[RPW];
#pragma unroll
            for (int r = 0; r < RPW; ++r) wv[r] = wb[r * 32];
#pragma unroll
            for (int t = 0; t < TCH; ++t) {
                ulonglong2 av = ab[t * 32];
#pragma unroll
                for (int r = 0; r < RPW; ++r) {
                    ffma2(acc[r][t], wv[r].x, av.x);
                    ffma2(acc[r][t], wv[r].y, av.y);
                }
            }
        }

        // ---- fold, warp-reduce, store ----
#pragma unroll
        for (int r = 0; r < RPW; ++r) {
#pragma unroll
            for (int t = 0; t < TCH; ++t) {
                float v = pair_sum(acc[r][t]);
                v += __shfl_xor_sync(0xFFFFFFFFu, v, 16);
                v += __shfl_xor_sync(0xFFFFFFFFu, v, 8);
                v += __shfl_xor_sync(0xFFFFFFFFu, v, 4);
                v += __shfl_xor_sync(0xFFFFFFFFu, v, 2);
                v += __shfl_xor_sync(0xFFFFFFFFu, v, 1);
                if (lane == 0 && (t0 + t) < cnt)
                    g_tmp[stok[t0 + t] * CC + c0 + warp * RPW + r] = v;
            }
        }
        __syncthreads();   // all stage reads done before next pass re-primes
    }
}

// ---------------------------------------------------------------------------
__global__ void finalize(const float* __restrict__ residual,
                         const float* __restrict__ bias,
                         const float* __restrict__ ew,
                         const int*  __restrict__ eidx,
                         float* __restrict__ out) {
    const int idx = blockIdx.x * blockDim.x + threadIdx.x;   // over BB*CC/4
    const int b   = idx / (CC / 4);
    const int c4  = idx % (CC / 4);

    const float4* r4 = reinterpret_cast<const float4*>(residual);
    const float4* b4 = reinterpret_cast<const float4*>(bias);
    const float4* t4 = reinterpret_cast<const float4*>(g_tmp);
    float4 v = r4[b * (CC / 4) + c4];
#pragma unroll
    for (int s = 0; s < TOPK; ++s) {
        const int   e = eidx[b * TOPK + s];
        const float w = ew[b * TOPK + s];
        float4 t  = t4[(b * TOPK + s) * (CC / 4) + c4];
        float4 bb = b4[e * (CC / 4) + c4];
        v.x += w * (t.x + bb.x);
        v.y += w * (t.y + bb.y);
        v.z += w * (t.z + bb.z);
        v.w += w * (t.w + bb.w);
    }
    reinterpret_cast<float4*>(out)[b * (CC / 4) + c4] = v;
}

__global__ void epilogue_nop() {}

// ---------------------------------------------------------------------------
extern "C" void kernel_launch(void* const* d_in, const int* in_sizes, int n_in,
                              void* d_out, int out_size) {
    const float* activated      = (const float*)d_in[0];
    const int*   expert_indices = (const int*)  d_in[1];
    const float* expert_weights = (const float*)d_in[2];
    const float* mlp2_weight    = (const float*)d_in[3];
    const float* mlp2_bias      = (const float*)d_in[4];
    const float* residual_x     = (const float*)d_in[5];
    float*       out            = (float*)d_out;

    static bool attr_done = false;
    if (!attr_done) {
        cudaFuncSetAttribute(matvec, cudaFuncAttributeMaxDynamicSharedMemorySize,
                             DYN_BYTES);
        attr_done = true;
    }

    dim3 grid(2, CC / CTILE, EE);   // chunk fastest -> L2 dedup of w re-reads
    matvec<<<grid, WARPS * 32, DYN_BYTES>>>(activated, mlp2_weight,
                                            expert_indices);

    finalize<<<(BB * CC / 4) / 256, 256>>>(residual_x, mlp2_bias,
                                           expert_weights, expert_indices, out);
    epilogue_nop<<<1, 1>>>();
}

// round 14
// speedup vs baseline: 1.2884x; 1.2884x over previous
#include <cuda_runtime.h>
#include <cstdint>

#define BB    64
#define TOPK  2
#define EE    16
#define CC    1024
#define KK    4096
#define NTOK  (BB * TOPK)     // 128

#define WARPS  4               // 128-thread CTA: 4-warp convergence domain
#define RPW    4               // rows per warp
#define TCH    8               // tokens per chunk
#define CTILE  (WARPS * RPW)   // 16 rows per CTA
#define K4     (KK / 4)        // 1024 float4 per row
#define JITERS (K4 / 32)       // 32 k-steps (512B per row per step)
#define NSTAGE 4               // power of two: ring math is & 3

// stage = w [CTILE][32] f4 + a [TCH][32] f4 = 768 f4 = 12KB
#define W_ST_F4   (CTILE * 32)                       // 512
#define A_ST_F4   (TCH * 32)                         // 256
#define ST_F4     (W_ST_F4 + A_ST_F4)                // 768
#define ST_BYTES  (ST_F4 * 16)                       // 12288
#define DYN_BYTES (NSTAGE * ST_BYTES)                // 49152

__device__ float g_tmp[NTOK * CC];

// ---- PTX helpers -----------------------------------------------------------
__device__ __forceinline__ void cp16(uint32_t dst, const void* src) {
    asm volatile("cp.async.cg.shared.global [%0], [%1], 16;"
                 :: "r"(dst), "l"(src) : "memory");
}
__device__ __forceinline__ void cp_commit() {
    asm volatile("cp.async.commit_group;" ::: "memory");
}
template <int N>
__device__ __forceinline__ void cp_wait() {
    asm volatile("cp.async.wait_group %0;" :: "n"(N) : "memory");
}
__device__ __forceinline__ void ffma2(unsigned long long& acc,
                                      unsigned long long w,
                                      unsigned long long a) {
    asm("fma.rn.f32x2 %0, %1, %2, %0;" : "+l"(acc) : "l"(w), "l"(a));
}
__device__ __forceinline__ float pair_sum(unsigned long long p) {
    float lo, hi;
    asm("mov.b64 {%0, %1}, %2;" : "=f"(lo), "=f"(hi) : "l"(p));
    return lo + hi;
}

// ---------------------------------------------------------------------------
// Grouped expert matvec (R11 proven config).
// Grid (2, CC/CTILE=64, EE=16): x = token-chunk (fastest: pair CTAs sharing a
// weight tile are bid-adjacent -> 2nd read hits L2), y = c-tile, z = expert.
// Block 128 (4 warps), 4 CTAs/SM. 4-stage cp.async ring for w AND a with
// per-(y,z) k-phase stagger. Fill/thread/j: 4 w rows + 2 a tokens. Consume:
// warp owns rows warp*4..+3 x all 8 tokens (64 FFMA2 / j).
// ---------------------------------------------------------------------------
__global__ void __launch_bounds__(128, 4)
matvec(const float* __restrict__ act,
       const float* __restrict__ W,
       const int*  __restrict__ eidx) {
    extern __shared__ float4 st[];            // [NSTAGE][768]

    __shared__ int se[NTOK];
    __shared__ int stok[NTOK];

    const int tid = threadIdx.x;
    const int e   = blockIdx.z;

    se[tid] = eidx[tid];                      // 128 threads == NTOK
    __syncthreads();
    int mine = (se[tid] == e);
    if (mine) {
        int pos = 0;
        for (int j = 0; j < tid; ++j) pos += (se[j] == e) ? 1 : 0;
        stok[pos] = tid;
    }
    const int cnt = __syncthreads_count(mine);
    if (cnt == 0) return;

    const int warp = tid >> 5;
    const int lane = tid & 31;
    const int c0   = blockIdx.y * CTILE;
    const int off  = (blockIdx.y + blockIdx.z * 5) & (JITERS - 1);  // k stagger

    const float4* __restrict__ wsrc =
        reinterpret_cast<const float4*>(W) + ((size_t)(e * CC + c0 + warp)) * K4 + lane;
    const uint32_t wdst0 =
        (uint32_t)__cvta_generic_to_shared(&st[(size_t)warp * 32 + lane]);
    const uint32_t adst0 =
        (uint32_t)__cvta_generic_to_shared(&st[(size_t)W_ST_F4 + warp * 64 + lane]);

    for (int t0 = blockIdx.x * TCH; t0 < cnt; t0 += 2 * TCH) {
        int ta0 = t0 + 2 * warp;     if (ta0 >= cnt) ta0 = cnt - 1;
        int ta1 = t0 + 2 * warp + 1; if (ta1 >= cnt) ta1 = cnt - 1;
        const float4* a0 =
            reinterpret_cast<const float4*>(act) + (size_t)stok[ta0] * K4 + lane;
        const float4* a1 =
            reinterpret_cast<const float4*>(act) + (size_t)stok[ta1] * K4 + lane;

        unsigned long long acc[RPW][TCH];
#pragma unroll
        for (int r = 0; r < RPW; ++r)
#pragma unroll
            for (int t = 0; t < TCH; ++t) acc[r][t] = 0ull;

        // ---- prime stages 0 .. NSTAGE-2 ----
#pragma unroll
        for (int s = 0; s < NSTAGE - 1; ++s) {
            const int ks = (s + off) & (JITERS - 1);
            const uint32_t d = wdst0 + s * ST_BYTES;
#pragma unroll
            for (int i = 0; i < 4; ++i)
                cp16(d + i * (4 * 512), wsrc + (size_t)(4 * i) * K4 + ks * 32);
            cp16(adst0 + s * ST_BYTES,       a0 + ks * 32);
            cp16(adst0 + s * ST_BYTES + 512, a1 + ks * 32);
            cp_commit();
        }

#pragma unroll 1
        for (int j = 0; j < JITERS; ++j) {
            cp_wait<NSTAGE - 2>();           // stage j ready; 2 groups in flight
            __syncthreads();                 // 4-warp convergence only

            const int jf = j + NSTAGE - 1;
            if (jf < JITERS) {
                const int kf = (jf + off) & (JITERS - 1);
                const uint32_t d = wdst0 + (jf & (NSTAGE - 1)) * ST_BYTES;
#pragma unroll
                for (int i = 0; i < 4; ++i)
                    cp16(d + i * (4 * 512), wsrc + (size_t)(4 * i) * K4 + kf * 32);
                const uint32_t da = adst0 + (jf & (NSTAGE - 1)) * ST_BYTES;
                cp16(da,       a0 + kf * 32);
                cp16(da + 512, a1 + kf * 32);
            }
            cp_commit();                     // commit every j: group counts aligned

            // ---- consume stage j & 3 ----
            const ulonglong2* base = reinterpret_cast<const ulonglong2*>(
                st + (size_t)(j & (NSTAGE - 1)) * ST_F4);
            const ulonglong2* wb = base + (warp * RPW) * 32 + lane;
            const ulonglong2* ab = base + W_ST_F4 + lane;

            ulonglong2 wv[RPW];
#pragma unroll
            for (int r = 0; r < RPW; ++r) wv[r] = wb[r * 32];
#pragma unroll
            for (int t = 0; t < TCH; ++t) {
                ulonglong2 av = ab[t * 32];
#pragma unroll
                for (int r = 0; r < RPW; ++r) {
                    ffma2(acc[r][t], wv[r].x, av.x);
                    ffma2(acc[r][t], wv[r].y, av.y);
                }
            }
        }

        // ---- fold, warp-reduce, store ----
#pragma unroll
        for (int r = 0; r < RPW; ++r) {
#pragma unroll
            for (int t = 0; t < TCH; ++t) {
                float v = pair_sum(acc[r][t]);
                v += __shfl_xor_sync(0xFFFFFFFFu, v, 16);
                v += __shfl_xor_sync(0xFFFFFFFFu, v, 8);
                v += __shfl_xor_sync(0xFFFFFFFFu, v, 4);
                v += __shfl_xor_sync(0xFFFFFFFFu, v, 2);
                v += __shfl_xor_sync(0xFFFFFFFFu, v, 1);
                if (lane == 0 && (t0 + t) < cnt)
                    g_tmp[stok[t0 + t] * CC + c0 + warp * RPW + r] = v;
            }
        }
        __syncthreads();   // all stage reads done before next chunk re-primes
    }
}

// ---------------------------------------------------------------------------
// finalize: out = residual + sum_s ew * (tmp + bias[e]) — float4, 128x128
// launch shape for better latency spread of this tiny tail kernel.
// ---------------------------------------------------------------------------
__global__ void __launch_bounds__(128)
finalize(const float* __restrict__ residual,
         const float* __restrict__ bias,
         const float* __restrict__ ew,
         const int*  __restrict__ eidx,
         float* __restrict__ out) {
    const int idx = blockIdx.x * blockDim.x + threadIdx.x;   // over BB*CC/4
    const int b   = idx >> 8;                                // CC/4 = 256
    const int c4  = idx & 255;

    const float4* r4 = reinterpret_cast<const float4*>(residual);
    const float4* b4 = reinterpret_cast<const float4*>(bias);
    const float4* t4 = reinterpret_cast<const float4*>(g_tmp);
    float4 v = r4[(b << 8) + c4];
#pragma unroll
    for (int s = 0; s < TOPK; ++s) {
        const int   e = eidx[b * TOPK + s];
        const float w = ew[b * TOPK + s];
        float4 t  = t4[((b * TOPK + s) << 8) + c4];
        float4 bb = b4[(e << 8) + c4];
        v.x += w * (t.x + bb.x);
        v.y += w * (t.y + bb.y);
        v.z += w * (t.z + bb.z);
        v.w += w * (t.w + bb.w);
    }
    reinterpret_cast<float4*>(out)[(b << 8) + c4] = v;
}

// ---------------------------------------------------------------------------
extern "C" void kernel_launch(void* const* d_in, const int* in_sizes, int n_in,
                              void* d_out, int out_size) {
    const float* activated      = (const float*)d_in[0];
    const int*   expert_indices = (const int*)  d_in[1];
    const float* expert_weights = (const float*)d_in[2];
    const float* mlp2_weight    = (const float*)d_in[3];
    const float* mlp2_bias      = (const float*)d_in[4];
    const float* residual_x     = (const float*)d_in[5];
    float*       out            = (float*)d_out;

    static bool attr_done = false;
    if (!attr_done) {
        cudaFuncSetAttribute(matvec, cudaFuncAttributeMaxDynamicSharedMemorySize,
                             DYN_BYTES);
        attr_done = true;
    }

    dim3 grid(2, CC / CTILE, EE);   // chunk fastest -> L2 dedup of w re-reads
    matvec<<<grid, WARPS * 32, DYN_BYTES>>>(activated, mlp2_weight,
                                            expert_indices);

    finalize<<<(BB * CC / 4) / 128, 128>>>(residual_x, mlp2_bias,
                                           expert_weights, expert_indices, out);
}